// round 2
// baseline (speedup 1.0000x reference)
#include <cuda_runtime.h>
#include <math.h>

// Problem constants (fixed by the dataset): B=32, C_in=C_out=128, H=W=64.
#define HW    4096          // 64*64
#define NPIX  131072        // 32*4096 pixels
#define NCH   128

// ---------------- scratch (device globals; no runtime allocation) ----------
__device__ float g_fmax[(size_t)NCH * NPIX];      // 64 MiB, x-layout [(b*128+c)*4096+hw]
__device__ float g_Y[(size_t)256 * NPIX];         // 128 MiB, [ch][pixel_global]
__device__ float g_H[(size_t)128 * NPIX];         // 64 MiB,  [ch][pixel_global]
__device__ float g_Wfold[128 * 256];
__device__ float g_ypart[256 * 1024 * 2];         // per (ch, pixel-tile): {sum, sumsq}
__device__ float g_hpart[128 * 1024 * 2];
__device__ float g_a[256];                        // g/sigma per Y channel (0..127: w_in/BN2, 128..255: w_diff/BN1)
__device__ float g_b2n[128];                      // beta2 - a2*mu2  (x_proc affine shift)
__device__ float g_a3[128];                       // g_mbn/sigma_h
__device__ float g_d3[128];                       // be_mbn - a3*mu_h

__device__ __forceinline__ float gelu_exact(float v) {
    return 0.5f * v * (1.0f + erff(v * 0.70710678118654752f));
}

// ---------------- K1: fmax = x - min over {self, row±s, col±s}, s in {2,4,8,16,32}
__global__ void k_fmax(const float* __restrict__ x) {
    __shared__ float sm[4096];
    int plane = blockIdx.x;                        // b*128 + c
    const float* xp = x + (size_t)plane * HW;
    float* fp = g_fmax + (size_t)plane * HW;
    for (int i = threadIdx.x; i < 4096; i += 256) sm[i] = xp[i];
    __syncthreads();
    for (int i = threadIdx.x; i < 4096; i += 256) {
        int h = i >> 6, w = i & 63;
        float v = sm[i];
        float m = v;
        #pragma unroll
        for (int s = 2; s <= 32; s <<= 1) {
            m = fminf(m, sm[(h << 6) | ((w + s) & 63)]);
            m = fminf(m, sm[(h << 6) | ((w - s) & 63)]);
            m = fminf(m, sm[((((h + s) & 63)) << 6) | w]);
            m = fminf(m, sm[((((h - s) & 63)) << 6) | w]);
        }
        fp[i] = v - m;
    }
}

// ---------------- K2: Y[o][p] = sum_k W[o][k] * X[k][p]  (K=128), + stat partials
// grid (1024 pixel-tiles, 2 out-tiles). out-tile 0: w_in applied to x; 1: w_diff to fmax.
__global__ __launch_bounds__(256, 2) void k_convY(
    const float* __restrict__ x, const float* __restrict__ w_in,
    const float* __restrict__ w_diff) {
    __shared__ float Ws[32][129];   // [k][o], padded: conflict-free transpose-store
    __shared__ float Xs[32][128];   // [k][p]
    const int ptile = blockIdx.x;
    const int otile = blockIdx.y;
    const float* W = otile ? w_diff : w_in;
    const float* X = otile ? (const float*)g_fmax : x;
    const int pglob = ptile * 128;
    const int b = pglob >> 12;                 // /4096 (tile never crosses a b plane)
    const int hw0 = pglob & 4095;
    const float* Xbase = X + (size_t)b * 128 * HW + hw0;   // + c*HW + p
    const int t = threadIdx.x;
    const int tx = t & 15, ty = t >> 4;        // channels: ty+16*i, pixels: tx*8+j

    float acc[8][8];
    #pragma unroll
    for (int i = 0; i < 8; i++)
        #pragma unroll
        for (int j = 0; j < 8; j++) acc[i][j] = 0.f;

    #pragma unroll 1
    for (int kc = 0; kc < 128; kc += 32) {
        #pragma unroll
        for (int r = 0; r < 16; r++) {
            int idx = t + r * 256;             // 4096 weights
            int o = idx >> 5, kk = idx & 31;
            Ws[kk][o] = W[o * 128 + kc + kk];
        }
        #pragma unroll
        for (int r = 0; r < 16; r++) {
            int idx = t + r * 256;             // 4096 activations
            int kk = idx >> 7, p = idx & 127;
            Xs[kk][p] = Xbase[(size_t)(kc + kk) * HW + p];
        }
        __syncthreads();
        #pragma unroll
        for (int k = 0; k < 32; k++) {
            float a[8];
            #pragma unroll
            for (int i = 0; i < 8; i++) a[i] = Ws[k][ty + 16 * i];
            float4 b0 = *(const float4*)&Xs[k][tx * 8];
            float4 b1 = *(const float4*)&Xs[k][tx * 8 + 4];
            float bb[8] = {b0.x, b0.y, b0.z, b0.w, b1.x, b1.y, b1.z, b1.w};
            #pragma unroll
            for (int i = 0; i < 8; i++)
                #pragma unroll
                for (int j = 0; j < 8; j++) acc[i][j] = fmaf(a[i], bb[j], acc[i][j]);
        }
        __syncthreads();
    }

    // epilogue: store Y + per-channel partial sums over this tile's 128 pixels
    float s1[8], s2[8];
    #pragma unroll
    for (int i = 0; i < 8; i++) { s1[i] = 0.f; s2[i] = 0.f; }
    #pragma unroll
    for (int i = 0; i < 8; i++) {
        int c = ty + 16 * i;
        float* Yrow = g_Y + (size_t)(otile * 128 + c) * NPIX + pglob + tx * 8;
        float4 v0 = make_float4(acc[i][0], acc[i][1], acc[i][2], acc[i][3]);
        float4 v1 = make_float4(acc[i][4], acc[i][5], acc[i][6], acc[i][7]);
        *(float4*)(Yrow) = v0;
        *(float4*)(Yrow + 4) = v1;
        #pragma unroll
        for (int j = 0; j < 8; j++) { float v = acc[i][j]; s1[i] += v; s2[i] += v * v; }
    }
    #pragma unroll
    for (int off = 8; off; off >>= 1)
        #pragma unroll
        for (int i = 0; i < 8; i++) {
            s1[i] += __shfl_down_sync(0xffffffffu, s1[i], off, 16);
            s2[i] += __shfl_down_sync(0xffffffffu, s2[i], off, 16);
        }
    if (tx == 0) {
        #pragma unroll
        for (int i = 0; i < 8; i++) {
            int c = otile * 128 + ty + 16 * i;
            g_ypart[((size_t)c * 1024 + ptile) * 2 + 0] = s1[i];
            g_ypart[((size_t)c * 1024 + ptile) * 2 + 1] = s2[i];
        }
    }
}

// ---------------- reduce Y stats -> a[256], b2n[128]
__global__ void k_reduceY(const float* __restrict__ g_ibn, const float* __restrict__ be_ibn,
                          const float* __restrict__ gbn) {
    int c = blockIdx.x;      // 0..255
    int t = threadIdx.x;     // 256
    double s = 0.0, ss = 0.0;
    for (int i = t; i < 1024; i += 256) {
        s  += (double)g_ypart[((size_t)c * 1024 + i) * 2 + 0];
        ss += (double)g_ypart[((size_t)c * 1024 + i) * 2 + 1];
    }
    __shared__ double sh[256], shh[256];
    sh[t] = s; shh[t] = ss; __syncthreads();
    for (int o = 128; o; o >>= 1) {
        if (t < o) { sh[t] += sh[t + o]; shh[t] += shh[t + o]; }
        __syncthreads();
    }
    if (t == 0) {
        double mu = sh[0] / (double)NPIX;
        double var = shh[0] / (double)NPIX - mu * mu;
        float g = (c < 128) ? g_ibn[c] : gbn[c - 128];
        float a = g / sqrtf((float)var + 1e-5f);
        g_a[c] = a;
        if (c < 128) g_b2n[c] = be_ibn[c] - a * (float)mu;
    }
}

// ---------------- fold a into w_mr
__global__ void k_wfold(const float* __restrict__ w_mr) {
    int i = blockIdx.x * 256 + threadIdx.x;   // 32768
    g_Wfold[i] = w_mr[i] * g_a[i & 255];
}

// ---------------- K4: H[o][p] = sum_k Wfold[o][k] * Y[k][p]  (K=256), + partials
__global__ __launch_bounds__(256, 2) void k_convH() {
    __shared__ float Ws[32][129];
    __shared__ float Xs[32][128];
    const int ptile = blockIdx.x;
    const int pglob = ptile * 128;
    const float* Xbase = g_Y + pglob;          // [ch][NPIX] layout: + c*NPIX + p
    const int t = threadIdx.x;
    const int tx = t & 15, ty = t >> 4;

    float acc[8][8];
    #pragma unroll
    for (int i = 0; i < 8; i++)
        #pragma unroll
        for (int j = 0; j < 8; j++) acc[i][j] = 0.f;

    #pragma unroll 1
    for (int kc = 0; kc < 256; kc += 32) {
        #pragma unroll
        for (int r = 0; r < 16; r++) {
            int idx = t + r * 256;
            int o = idx >> 5, kk = idx & 31;
            Ws[kk][o] = g_Wfold[o * 256 + kc + kk];
        }
        #pragma unroll
        for (int r = 0; r < 16; r++) {
            int idx = t + r * 256;
            int kk = idx >> 7, p = idx & 127;
            Xs[kk][p] = Xbase[(size_t)(kc + kk) * NPIX + p];
        }
        __syncthreads();
        #pragma unroll
        for (int k = 0; k < 32; k++) {
            float a[8];
            #pragma unroll
            for (int i = 0; i < 8; i++) a[i] = Ws[k][ty + 16 * i];
            float4 b0 = *(const float4*)&Xs[k][tx * 8];
            float4 b1 = *(const float4*)&Xs[k][tx * 8 + 4];
            float bb[8] = {b0.x, b0.y, b0.z, b0.w, b1.x, b1.y, b1.z, b1.w};
            #pragma unroll
            for (int i = 0; i < 8; i++)
                #pragma unroll
                for (int j = 0; j < 8; j++) acc[i][j] = fmaf(a[i], bb[j], acc[i][j]);
        }
        __syncthreads();
    }

    float s1[8], s2[8];
    #pragma unroll
    for (int i = 0; i < 8; i++) { s1[i] = 0.f; s2[i] = 0.f; }
    #pragma unroll
    for (int i = 0; i < 8; i++) {
        int c = ty + 16 * i;
        float* Hrow = g_H + (size_t)c * NPIX + pglob + tx * 8;
        *(float4*)(Hrow)     = make_float4(acc[i][0], acc[i][1], acc[i][2], acc[i][3]);
        *(float4*)(Hrow + 4) = make_float4(acc[i][4], acc[i][5], acc[i][6], acc[i][7]);
        #pragma unroll
        for (int j = 0; j < 8; j++) { float v = acc[i][j]; s1[i] += v; s2[i] += v * v; }
    }
    #pragma unroll
    for (int off = 8; off; off >>= 1)
        #pragma unroll
        for (int i = 0; i < 8; i++) {
            s1[i] += __shfl_down_sync(0xffffffffu, s1[i], off, 16);
            s2[i] += __shfl_down_sync(0xffffffffu, s2[i], off, 16);
        }
    if (tx == 0) {
        #pragma unroll
        for (int i = 0; i < 8; i++) {
            int c = ty + 16 * i;
            g_hpart[((size_t)c * 1024 + ptile) * 2 + 0] = s1[i];
            g_hpart[((size_t)c * 1024 + ptile) * 2 + 1] = s2[i];
        }
    }
}

// ---------------- reduce H stats -> a3, d3
__global__ void k_reduceH(const float* __restrict__ g_mbn, const float* __restrict__ be_mbn) {
    int c = blockIdx.x;      // 0..127
    int t = threadIdx.x;
    double s = 0.0, ss = 0.0;
    for (int i = t; i < 1024; i += 256) {
        s  += (double)g_hpart[((size_t)c * 1024 + i) * 2 + 0];
        ss += (double)g_hpart[((size_t)c * 1024 + i) * 2 + 1];
    }
    __shared__ double sh[256], shh[256];
    sh[t] = s; shh[t] = ss; __syncthreads();
    for (int o = 128; o; o >>= 1) {
        if (t < o) { sh[t] += sh[t + o]; shh[t] += shh[t + o]; }
        __syncthreads();
    }
    if (t == 0) {
        double mu = sh[0] / (double)NPIX;
        double var = shh[0] / (double)NPIX - mu * mu;
        float a = g_mbn[c] / sqrtf((float)var + 1e-5f);
        g_a3[c] = a;
        g_d3[c] = be_mbn[c] - a * (float)mu;
    }
}

// ---------------- K5: out = a2*Y2 + b2n + gelu(a3*H + d3)
__global__ void k_out(float* __restrict__ out) {
    size_t i = ((size_t)blockIdx.x * 256 + threadIdx.x) * 4;   // over 16777216
    int c = (int)((i >> 12) & 127);
    size_t b = i >> 19;                         // /(128*4096)
    size_t p = b * HW + (i & 4095);             // global pixel
    float4 y = *(const float4*)(g_Y + (size_t)c * NPIX + p);
    float4 h = *(const float4*)(g_H + (size_t)c * NPIX + p);
    float a2 = g_a[c], bn = g_b2n[c], a3 = g_a3[c], d3 = g_d3[c];
    float4 o;
    o.x = fmaf(a2, y.x, bn) + gelu_exact(fmaf(a3, h.x, d3));
    o.y = fmaf(a2, y.y, bn) + gelu_exact(fmaf(a3, h.y, d3));
    o.z = fmaf(a2, y.z, bn) + gelu_exact(fmaf(a3, h.z, d3));
    o.w = fmaf(a2, y.w, bn) + gelu_exact(fmaf(a3, h.w, d3));
    *(float4*)(out + i) = o;
}

// ---------------- launch ----------------------------------------------------
extern "C" void kernel_launch(void* const* d_in, const int* in_sizes, int n_in,
                              void* d_out, int out_size) {
    const float* x      = (const float*)d_in[0];
    const float* w_diff = (const float*)d_in[1];
    // d_in[2] b_diff: cancels in BN
    const float* gbn    = (const float*)d_in[3];
    // d_in[4] be_bn: x_diff shift cancels through BN3
    const float* w_in   = (const float*)d_in[5];
    // d_in[6] b_in: cancels in BN
    const float* g_ibn  = (const float*)d_in[7];
    const float* be_ibn = (const float*)d_in[8];
    const float* w_mr   = (const float*)d_in[9];
    // d_in[10] b_mr: cancels in BN3
    const float* g_mbn  = (const float*)d_in[11];
    const float* be_mbn = (const float*)d_in[12];
    float* out = (float*)d_out;

    k_fmax<<<4096, 256>>>(x);
    k_convY<<<dim3(1024, 2), 256>>>(x, w_in, w_diff);
    k_reduceY<<<256, 256>>>(g_ibn, be_ibn, gbn);
    k_wfold<<<128, 256>>>(w_mr);
    k_convH<<<1024, 256>>>();
    k_reduceH<<<128, 256>>>(g_mbn, be_mbn);
    k_out<<<16384, 256>>>(out);
}

// round 5
// speedup vs baseline: 1.7967x; 1.7967x over previous
#include <cuda_runtime.h>
#include <cuda_bf16.h>
#include <stdint.h>
#include <math.h>

#define HW    4096
#define NPIX  131072
#define NCH   128
#define NT    2048           // 64-pixel tiles
#define NCTA  148

typedef __nv_bfloat16 bf16;

__device__ bf16 g_xhi[(size_t)NCH * NPIX];
__device__ bf16 g_xlo[(size_t)NCH * NPIX];
__device__ bf16 g_fhi[(size_t)NCH * NPIX];
__device__ bf16 g_flo[(size_t)NCH * NPIX];
__device__ bf16 g_yhi[(size_t)256 * NPIX];
__device__ bf16 g_ylo[(size_t)256 * NPIX];
__device__ float g_H[(size_t)128 * NPIX];
__device__ float g_Wfold[128 * 256];
__device__ float g_ypart[256 * 296 * 2];
__device__ float g_hpart[128 * 296 * 2];
__device__ float g_a[256];
__device__ float g_b2n[128];
__device__ float g_a3[128];
__device__ float g_d3[128];

__device__ __forceinline__ uint32_t smem_u32(const void* p) {
    uint32_t a;
    asm("{ .reg .u64 t; cvta.to.shared.u64 t, %1; cvt.u32.u64 %0, t; }" : "=r"(a) : "l"(p));
    return a;
}
#define LDSM4(r, addr) \
    asm volatile("ldmatrix.sync.aligned.m8n8.x4.shared.b16 {%0,%1,%2,%3}, [%4];" \
        : "=r"((r)[0]), "=r"((r)[1]), "=r"((r)[2]), "=r"((r)[3]) : "r"(addr))
#define LDSM4T(r, addr) \
    asm volatile("ldmatrix.sync.aligned.m8n8.x4.trans.shared.b16 {%0,%1,%2,%3}, [%4];" \
        : "=r"((r)[0]), "=r"((r)[1]), "=r"((r)[2]), "=r"((r)[3]) : "r"(addr))
#define MMA(c, a, b0v, b1v) \
    asm volatile("mma.sync.aligned.m16n8k16.row.col.f32.bf16.bf16.f32 " \
        "{%0,%1,%2,%3},{%4,%5,%6,%7},{%8,%9},{%0,%1,%2,%3};" \
        : "+f"((c)[0]), "+f"((c)[1]), "+f"((c)[2]), "+f"((c)[3]) \
        : "r"((a)[0]), "r"((a)[1]), "r"((a)[2]), "r"((a)[3]), "r"(b0v), "r"(b1v))
#define CPA16(s, g) asm volatile("cp.async.cg.shared.global [%0], [%1], 16;" :: "r"(s), "l"(g))
#define CPC()       asm volatile("cp.async.commit_group;" ::: "memory")
#define CPW0()      asm volatile("cp.async.wait_group 0;" ::: "memory")

__device__ __forceinline__ float gelu(float v) { return 0.5f * v * (1.0f + erff(v * 0.70710678f)); }
__device__ __forceinline__ void split(float v, bf16& h, bf16& l) {
    h = __float2bfloat16(v); l = __float2bfloat16(v - __bfloat162float(h));
}

// ---- K1: fmax + bf16 splits of x and fmax ----
__global__ void k_fmax(const float* __restrict__ x) {
    __shared__ float sm[4096];
    size_t o = (size_t)blockIdx.x * HW;
    for (int i = threadIdx.x; i < 4096; i += 256) sm[i] = x[o + i];
    __syncthreads();
    for (int i = threadIdx.x; i < 4096; i += 256) {
        int h = i >> 6, w = i & 63;
        float v = sm[i], m = v;
        #pragma unroll
        for (int s = 2; s <= 32; s <<= 1) {
            m = fminf(m, sm[(h << 6) | ((w + s) & 63)]);
            m = fminf(m, sm[(h << 6) | ((w - s) & 63)]);
            m = fminf(m, sm[(((h + s) & 63) << 6) | w]);
            m = fminf(m, sm[(((h - s) & 63) << 6) | w]);
        }
        float d = v - m;
        split(v, g_xhi[o + i], g_xlo[o + i]);
        split(d, g_fhi[o + i], g_flo[o + i]);
    }
}

// ============ GEMM-Y: Y[128ch][64px tile] = W[128x128] * X, 3 split passes =====
// SMEM layout (bytes): Ahi[128][136] @0 (34816), Alo @34816,
//                      Bhi[128][72]  @69632 (18432), Blo @88064. total 106496.
#define Y_AS   136
#define Y_BS   72
#define Y_ALO  34816u
#define Y_BHI  69632u
#define Y_BLO  88064u
#define SM_Y   106496

__global__ __launch_bounds__(256, 2) void k_gemmY(const float* __restrict__ w_in,
                                                  const float* __restrict__ w_diff) {
    extern __shared__ __align__(16) char smem[];
    const uint32_t sb = smem_u32(smem);
    const int tid = threadIdx.x;
    const int lane = tid & 31, wid = tid >> 5;
    const int wr = wid >> 1, wc = wid & 1;          // 4x2 warp grid
    const int cta = blockIdx.x, ot = blockIdx.y;
    const float* W = ot ? w_diff : w_in;
    const bf16* Shi = ot ? g_fhi : g_xhi;
    const bf16* Slo = ot ? g_flo : g_xlo;

    // weights -> smem (hi/lo), padded rows
    for (int idx = tid; idx < 128 * 128; idx += 256) {
        int m = idx >> 7, k = idx & 127;
        bf16 h, l; split(W[idx], h, l);
        *(bf16*)(smem + (m * Y_AS + k) * 2) = h;
        *(bf16*)(smem + Y_ALO + (m * Y_AS + k) * 2) = l;
    }
    __syncthreads();

    const int la = lane & 15, lb = lane >> 4;
    const int mb = wr * 32, nb = wc * 32;
    // ldmatrix lane base addresses
    const uint32_t aBase = sb + (uint32_t)((mb + la) * Y_AS * 2 + lb * 16);
    const uint32_t bBase = sb + Y_BHI + (uint32_t)(la * Y_BS * 2 + (nb + lb * 8) * 2);

    float st1[4] = {0.f, 0.f, 0.f, 0.f}, st2[4] = {0.f, 0.f, 0.f, 0.f};

    for (int t = cta; t < NT; t += NCTA) {
        // load B tile (hi & lo): 128 k-rows x 64 px
        {
            int p0 = t * 64;
            size_t base = (size_t)(p0 >> 12) * 128 * HW + (p0 & 4095);
            #pragma unroll
            for (int rq = 0; rq < 4; rq++) {
                int q = tid + rq * 256;          // 0..1023
                int k = q >> 3, c8 = q & 7;
                uint32_t d = sb + Y_BHI + (uint32_t)(k * Y_BS * 2 + c8 * 16);
                const bf16* src = Shi + base + (size_t)k * HW + c8 * 8;
                CPA16(d, src);
                CPA16(d + (Y_BLO - Y_BHI), Slo + base + (size_t)k * HW + c8 * 8);
            }
            CPC(); CPW0();
        }
        __syncthreads();

        float c[2][4][4];
        #pragma unroll
        for (int i = 0; i < 2; i++)
            #pragma unroll
            for (int j = 0; j < 4; j++)
                #pragma unroll
                for (int q = 0; q < 4; q++) c[i][j][q] = 0.f;

        #pragma unroll 1
        for (int p3 = 0; p3 < 3; p3++) {
            uint32_t aA = aBase + (p3 == 2 ? Y_ALO : 0u);
            uint32_t bA = bBase + (p3 == 1 ? (Y_BLO - Y_BHI) : 0u);
            #pragma unroll
            for (int ks = 0; ks < 8; ks++) {
                uint32_t a0[4], a1[4], b0[4], b1[4];
                LDSM4(a0, aA + ks * 32);
                LDSM4(a1, aA + ks * 32 + 16 * Y_AS * 2);
                LDSM4T(b0, bA + ks * (16 * Y_BS * 2));
                LDSM4T(b1, bA + ks * (16 * Y_BS * 2) + 32);
                MMA(c[0][0], a0, b0[0], b0[1]);
                MMA(c[0][1], a0, b0[2], b0[3]);
                MMA(c[0][2], a0, b1[0], b1[1]);
                MMA(c[0][3], a0, b1[2], b1[3]);
                MMA(c[1][0], a1, b0[0], b0[1]);
                MMA(c[1][1], a1, b0[2], b0[3]);
                MMA(c[1][2], a1, b1[0], b1[1]);
                MMA(c[1][3], a1, b1[2], b1[3]);
            }
        }
        __syncthreads();   // mma done reading smem before next tile's cp.async

        // epilogue: split-store + stats. thread owns ch = mb+i*16+(lane>>2)+{0,8}
        int p0 = t * 64;
        int r = lane >> 2, cq = (lane & 3) * 2;
        #pragma unroll
        for (int i = 0; i < 2; i++) {
            int chA = ot * 128 + mb + i * 16 + r;
            size_t gA = (size_t)chA * NPIX + p0;
            size_t gB = gA + (size_t)8 * NPIX;
            #pragma unroll
            for (int j = 0; j < 4; j++) {
                int n = nb + j * 8 + cq;
                float v0 = c[i][j][0], v1 = c[i][j][1], v2 = c[i][j][2], v3 = c[i][j][3];
                st1[i * 2]     += v0 + v1; st2[i * 2]     += v0 * v0 + v1 * v1;
                st1[i * 2 + 1] += v2 + v3; st2[i * 2 + 1] += v2 * v2 + v3 * v3;
                bf16 h0, l0, h1, l1;
                split(v0, h0, l0); split(v1, h1, l1);
                __nv_bfloat162 hh; hh.x = h0; hh.y = h1;
                __nv_bfloat162 ll; ll.x = l0; ll.y = l1;
                *(__nv_bfloat162*)(g_yhi + gA + n) = hh;
                *(__nv_bfloat162*)(g_ylo + gA + n) = ll;
                split(v2, h0, l0); split(v3, h1, l1);
                hh.x = h0; hh.y = h1; ll.x = l0; ll.y = l1;
                *(__nv_bfloat162*)(g_yhi + gB + n) = hh;
                *(__nv_bfloat162*)(g_ylo + gB + n) = ll;
            }
        }
    }

    // reduce stats over the 4-lane n-group (lane&3), then write partials
    #pragma unroll
    for (int s = 0; s < 4; s++) {
        #pragma unroll
        for (int d = 1; d < 4; d <<= 1) {
            st1[s] += __shfl_xor_sync(0xffffffffu, st1[s], d);
            st2[s] += __shfl_xor_sync(0xffffffffu, st2[s], d);
        }
    }
    if ((lane & 3) == 0) {
        int r = lane >> 2;
        int col = cta * 2 + wc;
        #pragma unroll
        for (int s = 0; s < 4; s++) {
            int ch = ot * 128 + wr * 32 + (s >> 1) * 16 + r + (s & 1) * 8;
            g_ypart[((size_t)ch * 296 + col) * 2 + 0] = st1[s];
            g_ypart[((size_t)ch * 296 + col) * 2 + 1] = st2[s];
        }
    }
}

// ---- reduce Y stats -> a[256], b2n[128] ----
__global__ void k_reduceY(const float* __restrict__ g_ibn, const float* __restrict__ be_ibn,
                          const float* __restrict__ gbn) {
    int c = blockIdx.x, t = threadIdx.x;   // 256 blocks x 128 threads
    double s = 0.0, ss = 0.0;
    for (int i = t; i < 296; i += 128) {
        s  += (double)g_ypart[((size_t)c * 296 + i) * 2 + 0];
        ss += (double)g_ypart[((size_t)c * 296 + i) * 2 + 1];
    }
    __shared__ double sh[128], shh[128];
    sh[t] = s; shh[t] = ss; __syncthreads();
    for (int o = 64; o; o >>= 1) {
        if (t < o) { sh[t] += sh[t + o]; shh[t] += shh[t + o]; }
        __syncthreads();
    }
    if (t == 0) {
        double mu = sh[0] / (double)NPIX;
        double var = shh[0] / (double)NPIX - mu * mu;
        float g = (c < 128) ? g_ibn[c] : gbn[c - 128];
        float a = g / sqrtf((float)var + 1e-5f);
        g_a[c] = a;
        if (c < 128) g_b2n[c] = be_ibn[c] - a * (float)mu;
    }
}

__global__ void k_wfold(const float* __restrict__ w_mr) {
    int i = blockIdx.x * 256 + threadIdx.x;
    g_Wfold[i] = w_mr[i] * g_a[i & 255];
}

// ============ GEMM-H: H[128][64px] = Wfold[128x256] * Ycat, 3 split passes =====
// Ahi[128][264] @0 (67584), Alo @67584, Bhi[256][72] @135168 (36864), Blo @172032.
#define H_AS   264
#define H_BS   72
#define H_ALO  67584u
#define H_BHI  135168u
#define H_BLO  172032u
#define SM_H   208896

__global__ __launch_bounds__(256, 1) void k_gemmH() {
    extern __shared__ __align__(16) char smem[];
    const uint32_t sb = smem_u32(smem);
    const int tid = threadIdx.x;
    const int lane = tid & 31, wid = tid >> 5;
    const int wr = wid >> 1, wc = wid & 1;
    const int cta = blockIdx.x;

    for (int idx = tid; idx < 128 * 256; idx += 256) {
        int m = idx >> 8, k = idx & 255;
        bf16 h, l; split(g_Wfold[idx], h, l);
        *(bf16*)(smem + (m * H_AS + k) * 2) = h;
        *(bf16*)(smem + H_ALO + (m * H_AS + k) * 2) = l;
    }
    __syncthreads();

    const int la = lane & 15, lb = lane >> 4;
    const int mb = wr * 32, nb = wc * 32;
    const uint32_t aBase = sb + (uint32_t)((mb + la) * H_AS * 2 + lb * 16);
    const uint32_t bBase = sb + H_BHI + (uint32_t)(la * H_BS * 2 + (nb + lb * 8) * 2);

    float st1[4] = {0.f, 0.f, 0.f, 0.f}, st2[4] = {0.f, 0.f, 0.f, 0.f};

    for (int t = cta; t < NT; t += NCTA) {
        int p0 = t * 64;
        #pragma unroll
        for (int rq = 0; rq < 8; rq++) {
            int q = tid + rq * 256;              // 0..2047
            int k = q >> 3, c8 = q & 7;
            uint32_t d = sb + H_BHI + (uint32_t)(k * H_BS * 2 + c8 * 16);
            CPA16(d, g_yhi + (size_t)k * NPIX + p0 + c8 * 8);
            CPA16(d + (H_BLO - H_BHI), g_ylo + (size_t)k * NPIX + p0 + c8 * 8);
        }
        CPC(); CPW0();
        __syncthreads();

        float c[2][4][4];
        #pragma unroll
        for (int i = 0; i < 2; i++)
            #pragma unroll
            for (int j = 0; j < 4; j++)
                #pragma unroll
                for (int q = 0; q < 4; q++) c[i][j][q] = 0.f;

        #pragma unroll 1
        for (int p3 = 0; p3 < 3; p3++) {
            uint32_t aA = aBase + (p3 == 2 ? H_ALO : 0u);
            uint32_t bA = bBase + (p3 == 1 ? (H_BLO - H_BHI) : 0u);
            #pragma unroll
            for (int ks = 0; ks < 16; ks++) {
                uint32_t a0[4], a1[4], b0[4], b1[4];
                LDSM4(a0, aA + ks * 32);
                LDSM4(a1, aA + ks * 32 + 16 * H_AS * 2);
                LDSM4T(b0, bA + ks * (16 * H_BS * 2));
                LDSM4T(b1, bA + ks * (16 * H_BS * 2) + 32);
                MMA(c[0][0], a0, b0[0], b0[1]);
                MMA(c[0][1], a0, b0[2], b0[3]);
                MMA(c[0][2], a0, b1[0], b1[1]);
                MMA(c[0][3], a0, b1[2], b1[3]);
                MMA(c[1][0], a1, b0[0], b0[1]);
                MMA(c[1][1], a1, b0[2], b0[3]);
                MMA(c[1][2], a1, b1[0], b1[1]);
                MMA(c[1][3], a1, b1[2], b1[3]);
            }
        }
        __syncthreads();

        int r = lane >> 2, cq = (lane & 3) * 2;
        #pragma unroll
        for (int i = 0; i < 2; i++) {
            int chA = mb + i * 16 + r;
            float* gA = g_H + (size_t)chA * NPIX + p0;
            float* gB = gA + (size_t)8 * NPIX;
            #pragma unroll
            for (int j = 0; j < 4; j++) {
                int n = nb + j * 8 + cq;
                float v0 = c[i][j][0], v1 = c[i][j][1], v2 = c[i][j][2], v3 = c[i][j][3];
                st1[i * 2]     += v0 + v1; st2[i * 2]     += v0 * v0 + v1 * v1;
                st1[i * 2 + 1] += v2 + v3; st2[i * 2 + 1] += v2 * v2 + v3 * v3;
                float2 f0; f0.x = v0; f0.y = v1;
                float2 f1; f1.x = v2; f1.y = v3;
                *(float2*)(gA + n) = f0;
                *(float2*)(gB + n) = f1;
            }
        }
    }

    #pragma unroll
    for (int s = 0; s < 4; s++) {
        #pragma unroll
        for (int d = 1; d < 4; d <<= 1) {
            st1[s] += __shfl_xor_sync(0xffffffffu, st1[s], d);
            st2[s] += __shfl_xor_sync(0xffffffffu, st2[s], d);
        }
    }
    if ((lane & 3) == 0) {
        int r = lane >> 2;
        int col = cta * 2 + wc;
        #pragma unroll
        for (int s = 0; s < 4; s++) {
            int ch = wr * 32 + (s >> 1) * 16 + r + (s & 1) * 8;
            g_hpart[((size_t)ch * 296 + col) * 2 + 0] = st1[s];
            g_hpart[((size_t)ch * 296 + col) * 2 + 1] = st2[s];
        }
    }
}

// ---- reduce H stats -> a3, d3 ----
__global__ void k_reduceH(const float* __restrict__ g_mbn, const float* __restrict__ be_mbn) {
    int c = blockIdx.x, t = threadIdx.x;  // 128 x 128
    double s = 0.0, ss = 0.0;
    for (int i = t; i < 296; i += 128) {
        s  += (double)g_hpart[((size_t)c * 296 + i) * 2 + 0];
        ss += (double)g_hpart[((size_t)c * 296 + i) * 2 + 1];
    }
    __shared__ double sh[128], shh[128];
    sh[t] = s; shh[t] = ss; __syncthreads();
    for (int o = 64; o; o >>= 1) {
        if (t < o) { sh[t] += sh[t + o]; shh[t] += shh[t + o]; }
        __syncthreads();
    }
    if (t == 0) {
        double mu = sh[0] / (double)NPIX;
        double var = shh[0] / (double)NPIX - mu * mu;
        float a = g_mbn[c] / sqrtf((float)var + 1e-5f);
        g_a3[c] = a;
        g_d3[c] = be_mbn[c] - a * (float)mu;
    }
}

// ---- out = a2*(yhi+ylo) + b2n + gelu(a3*H + d3) ----
__global__ void k_out(float* __restrict__ out) {
    size_t i = ((size_t)blockIdx.x * 256 + threadIdx.x) * 4;
    int c = (int)((i >> 12) & 127);
    size_t b = i >> 19;
    size_t p = b * HW + (i & 4095);
    float4 h = *(const float4*)(g_H + (size_t)c * NPIX + p);
    __nv_bfloat162 yh0 = *(const __nv_bfloat162*)(g_yhi + (size_t)c * NPIX + p);
    __nv_bfloat162 yh1 = *(const __nv_bfloat162*)(g_yhi + (size_t)c * NPIX + p + 2);
    __nv_bfloat162 yl0 = *(const __nv_bfloat162*)(g_ylo + (size_t)c * NPIX + p);
    __nv_bfloat162 yl1 = *(const __nv_bfloat162*)(g_ylo + (size_t)c * NPIX + p + 2);
    float a2 = g_a[c], bn = g_b2n[c], a3 = g_a3[c], d3 = g_d3[c];
    float4 o;
    o.x = fmaf(a2, __bfloat162float(yh0.x) + __bfloat162float(yl0.x), bn) + gelu(fmaf(a3, h.x, d3));
    o.y = fmaf(a2, __bfloat162float(yh0.y) + __bfloat162float(yl0.y), bn) + gelu(fmaf(a3, h.y, d3));
    o.z = fmaf(a2, __bfloat162float(yh1.x) + __bfloat162float(yl1.x), bn) + gelu(fmaf(a3, h.z, d3));
    o.w = fmaf(a2, __bfloat162float(yh1.y) + __bfloat162float(yl1.y), bn) + gelu(fmaf(a3, h.w, d3));
    *(float4*)(out + i) = o;
}

extern "C" void kernel_launch(void* const* d_in, const int* in_sizes, int n_in,
                              void* d_out, int out_size) {
    const float* x      = (const float*)d_in[0];
    const float* w_diff = (const float*)d_in[1];
    const float* gbn    = (const float*)d_in[3];
    const float* w_in   = (const float*)d_in[5];
    const float* g_ibn  = (const float*)d_in[7];
    const float* be_ibn = (const float*)d_in[8];
    const float* w_mr   = (const float*)d_in[9];
    const float* g_mbn  = (const float*)d_in[11];
    const float* be_mbn = (const float*)d_in[12];
    float* out = (float*)d_out;

    cudaFuncSetAttribute(k_gemmY, cudaFuncAttributeMaxDynamicSharedMemorySize, SM_Y);
    cudaFuncSetAttribute(k_gemmH, cudaFuncAttributeMaxDynamicSharedMemorySize, SM_H);

    k_fmax<<<4096, 256>>>(x);
    k_gemmY<<<dim3(NCTA, 2), 256, SM_Y>>>(w_in, w_diff);
    k_reduceY<<<256, 128>>>(g_ibn, be_ibn, gbn);
    k_wfold<<<128, 256>>>(w_mr);
    k_gemmH<<<NCTA, 256, SM_H>>>();
    k_reduceH<<<128, 128>>>(g_mbn, be_mbn);
    k_out<<<16384, 256>>>(out);
}

// round 7
// speedup vs baseline: 2.4089x; 1.3407x over previous
#include <cuda_runtime.h>
#include <cuda_fp16.h>
#include <stdint.h>
#include <math.h>

#define HW    4096
#define NPIX  131072
#define NCH   128
#define NT    2048           // 64-pixel tiles
#define NCTA  148

__device__ __half g_xh[(size_t)NCH * NPIX];     // x as fp16
__device__ __half g_fh[(size_t)NCH * NPIX];     // fmax as fp16
__device__ __half g_yh[(size_t)256 * NPIX];     // Y as fp16 (all 256 ch)
__device__ __half g_yl[(size_t)128 * NPIX];     // Y residual, ch 0..127 only (for x_proc)
__device__ float g_H[(size_t)128 * NPIX];
__device__ float g_Wfold[128 * 256];
__device__ float g_ypart[256 * 296 * 2];
__device__ float g_hpart[128 * 296 * 2];
__device__ float g_a[256];
__device__ float g_b2n[128];
__device__ float g_a3[128];
__device__ float g_d3[128];

__device__ __forceinline__ uint32_t smem_u32(const void* p) {
    uint32_t a;
    asm("{ .reg .u64 t; cvta.to.shared.u64 t, %1; cvt.u32.u64 %0, t; }" : "=r"(a) : "l"(p));
    return a;
}
#define LDSM4(r, addr) \
    asm volatile("ldmatrix.sync.aligned.m8n8.x4.shared.b16 {%0,%1,%2,%3}, [%4];" \
        : "=r"((r)[0]), "=r"((r)[1]), "=r"((r)[2]), "=r"((r)[3]) : "r"(addr))
#define LDSM4T(r, addr) \
    asm volatile("ldmatrix.sync.aligned.m8n8.x4.trans.shared.b16 {%0,%1,%2,%3}, [%4];" \
        : "=r"((r)[0]), "=r"((r)[1]), "=r"((r)[2]), "=r"((r)[3]) : "r"(addr))
#define MMA(c, a, b0v, b1v) \
    asm volatile("mma.sync.aligned.m16n8k16.row.col.f32.f16.f16.f32 " \
        "{%0,%1,%2,%3},{%4,%5,%6,%7},{%8,%9},{%0,%1,%2,%3};" \
        : "+f"((c)[0]), "+f"((c)[1]), "+f"((c)[2]), "+f"((c)[3]) \
        : "r"((a)[0]), "r"((a)[1]), "r"((a)[2]), "r"((a)[3]), "r"(b0v), "r"(b1v))
#define CPA16(s, g) asm volatile("cp.async.cg.shared.global [%0], [%1], 16;" :: "r"(s), "l"(g))
#define CPC()       asm volatile("cp.async.commit_group;" ::: "memory")
#define CPW1()      asm volatile("cp.async.wait_group 1;" ::: "memory")

__device__ __forceinline__ float gelu(float v) { return 0.5f * v * (1.0f + erff(v * 0.70710678f)); }
__device__ __forceinline__ void hsplit(float v, __half& h, __half& l) {
    h = __float2half_rn(v); l = __float2half_rn(v - __half2float(h));
}

// ---- K1: fmax; write x and fmax as single fp16 ----
__global__ void k_fmax(const float* __restrict__ x) {
    __shared__ float sm[4096];
    size_t o = (size_t)blockIdx.x * HW;
    for (int i = threadIdx.x; i < 4096; i += 256) sm[i] = x[o + i];
    __syncthreads();
    for (int i = threadIdx.x; i < 4096; i += 256) {
        int h = i >> 6, w = i & 63;
        float v = sm[i], m = v;
        #pragma unroll
        for (int s = 2; s <= 32; s <<= 1) {
            m = fminf(m, sm[(h << 6) | ((w + s) & 63)]);
            m = fminf(m, sm[(h << 6) | ((w - s) & 63)]);
            m = fminf(m, sm[(((h + s) & 63) << 6) | w]);
            m = fminf(m, sm[(((h - s) & 63) << 6) | w]);
        }
        g_xh[o + i] = __float2half_rn(v);
        g_fh[o + i] = __float2half_rn(v - m);
    }
}

// ============ GEMM-Y: Y[128ch][64px] = (Wh+Wl)[128x128] * Xh, 2 passes ========
#define Y_AS   136
#define Y_BS   72
#define Y_ALO  34816u
#define Y_B0   69632u
#define Y_BSZ  18432u
#define SM_Y   106496

__global__ __launch_bounds__(256, 2) void k_gemmY(const float* __restrict__ w_in,
                                                  const float* __restrict__ w_diff) {
    extern __shared__ __align__(16) char smem[];
    const uint32_t sb = smem_u32(smem);
    const int tid = threadIdx.x;
    const int lane = tid & 31, wid = tid >> 5;
    const int wr = wid >> 1, wc = wid & 1;          // 4x2 warp grid
    const int cta = blockIdx.x, ot = blockIdx.y;
    const float* W = ot ? w_diff : w_in;
    const __half* S = ot ? g_fh : g_xh;

    for (int idx = tid; idx < 128 * 128; idx += 256) {
        int m = idx >> 7, k = idx & 127;
        __half h, l; hsplit(W[idx], h, l);
        *(__half*)(smem + (m * Y_AS + k) * 2) = h;
        *(__half*)(smem + Y_ALO + (m * Y_AS + k) * 2) = l;
    }
    __syncthreads();

    const int la = lane & 15, lb = lane >> 4;
    const int mb = wr * 32, nb = wc * 32;
    const uint32_t aBase = sb + (uint32_t)((mb + la) * Y_AS * 2 + lb * 16);
    const uint32_t bBase = sb + Y_B0 + (uint32_t)(la * Y_BS * 2 + (nb + lb * 8) * 2);

    float st1[4] = {0.f, 0.f, 0.f, 0.f}, st2[4] = {0.f, 0.f, 0.f, 0.f};
    int buf = 0;

    {   // prefetch first tile -> buf0
        int p0 = cta * 64;
        size_t base = (size_t)(p0 >> 12) * 128 * HW + (p0 & 4095);
        #pragma unroll
        for (int rq = 0; rq < 4; rq++) {
            int q = tid + rq * 256;
            int k = q >> 3, c8 = q & 7;
            CPA16(sb + Y_B0 + (uint32_t)(k * Y_BS * 2 + c8 * 16),
                  S + base + (size_t)k * HW + c8 * 8);
        }
        CPC();
    }

    for (int t = cta; t < NT; t += NCTA) {
        int tn = t + NCTA;
        if (tn < NT) {
            int p0n = tn * 64;
            size_t base = (size_t)(p0n >> 12) * 128 * HW + (p0n & 4095);
            uint32_t bo = Y_B0 + (uint32_t)(buf ^ 1) * Y_BSZ;
            #pragma unroll
            for (int rq = 0; rq < 4; rq++) {
                int q = tid + rq * 256;
                int k = q >> 3, c8 = q & 7;
                CPA16(sb + bo + (uint32_t)(k * Y_BS * 2 + c8 * 16),
                      S + base + (size_t)k * HW + c8 * 8);
            }
        }
        CPC(); CPW1();
        __syncthreads();

        float c[2][4][4];
        #pragma unroll
        for (int i = 0; i < 2; i++)
            #pragma unroll
            for (int j = 0; j < 4; j++)
                #pragma unroll
                for (int q = 0; q < 4; q++) c[i][j][q] = 0.f;

        uint32_t bA = bBase + (uint32_t)buf * Y_BSZ;
        #pragma unroll 1
        for (int p2 = 0; p2 < 2; p2++) {
            uint32_t aA = aBase + (p2 ? Y_ALO : 0u);
            #pragma unroll
            for (int ks = 0; ks < 8; ks++) {
                uint32_t a0[4], a1[4], b0[4], b1[4];
                LDSM4(a0, aA + ks * 32);
                LDSM4(a1, aA + ks * 32 + 16 * Y_AS * 2);
                LDSM4T(b0, bA + ks * (16 * Y_BS * 2));
                LDSM4T(b1, bA + ks * (16 * Y_BS * 2) + 32);
                MMA(c[0][0], a0, b0[0], b0[1]);
                MMA(c[0][1], a0, b0[2], b0[3]);
                MMA(c[0][2], a0, b1[0], b1[1]);
                MMA(c[0][3], a0, b1[2], b1[3]);
                MMA(c[1][0], a1, b0[0], b0[1]);
                MMA(c[1][1], a1, b0[2], b0[3]);
                MMA(c[1][2], a1, b1[0], b1[1]);
                MMA(c[1][3], a1, b1[2], b1[3]);
            }
        }
        __syncthreads();    // all reads of buf done before refill at t+2

        int p0 = t * 64;
        int r = lane >> 2, cq = (lane & 3) * 2;
        #pragma unroll
        for (int i = 0; i < 2; i++) {
            int chA = ot * 128 + mb + i * 16 + r;
            size_t gA = (size_t)chA * NPIX + p0;
            size_t gB = gA + (size_t)8 * NPIX;
            #pragma unroll
            for (int j = 0; j < 4; j++) {
                int n = nb + j * 8 + cq;
                float v0 = c[i][j][0], v1 = c[i][j][1], v2 = c[i][j][2], v3 = c[i][j][3];
                st1[i * 2]     += v0 + v1; st2[i * 2]     += v0 * v0 + v1 * v1;
                st1[i * 2 + 1] += v2 + v3; st2[i * 2 + 1] += v2 * v2 + v3 * v3;
                __half h0, l0, h1, l1;
                hsplit(v0, h0, l0); hsplit(v1, h1, l1);
                __half2 hh; hh.x = h0; hh.y = h1;
                *(__half2*)(g_yh + gA + n) = hh;
                if (ot == 0) { __half2 ll; ll.x = l0; ll.y = l1; *(__half2*)(g_yl + gA + n) = ll; }
                hsplit(v2, h0, l0); hsplit(v3, h1, l1);
                hh.x = h0; hh.y = h1;
                *(__half2*)(g_yh + gB + n) = hh;
                if (ot == 0) { __half2 ll; ll.x = l0; ll.y = l1; *(__half2*)(g_yl + gB + n) = ll; }
            }
        }
        buf ^= 1;           // <-- the Round-6 bug: this was missing
    }

    #pragma unroll
    for (int s = 0; s < 4; s++) {
        #pragma unroll
        for (int d = 1; d < 4; d <<= 1) {
            st1[s] += __shfl_xor_sync(0xffffffffu, st1[s], d);
            st2[s] += __shfl_xor_sync(0xffffffffu, st2[s], d);
        }
    }
    if ((lane & 3) == 0) {
        int r = lane >> 2;
        int col = cta * 2 + wc;
        #pragma unroll
        for (int s = 0; s < 4; s++) {
            int ch = ot * 128 + wr * 32 + (s >> 1) * 16 + r + (s & 1) * 8;
            g_ypart[((size_t)ch * 296 + col) * 2 + 0] = st1[s];
            g_ypart[((size_t)ch * 296 + col) * 2 + 1] = st2[s];
        }
    }
}

// ---- reduce Y stats -> a[256], b2n[128] ----
__global__ void k_reduceY(const float* __restrict__ g_ibn, const float* __restrict__ be_ibn,
                          const float* __restrict__ gbn) {
    int c = blockIdx.x, t = threadIdx.x;
    double s = 0.0, ss = 0.0;
    for (int i = t; i < 296; i += 128) {
        s  += (double)g_ypart[((size_t)c * 296 + i) * 2 + 0];
        ss += (double)g_ypart[((size_t)c * 296 + i) * 2 + 1];
    }
    __shared__ double sh[128], shh[128];
    sh[t] = s; shh[t] = ss; __syncthreads();
    for (int o = 64; o; o >>= 1) {
        if (t < o) { sh[t] += sh[t + o]; shh[t] += shh[t + o]; }
        __syncthreads();
    }
    if (t == 0) {
        double mu = sh[0] / (double)NPIX;
        double var = shh[0] / (double)NPIX - mu * mu;
        float g = (c < 128) ? g_ibn[c] : gbn[c - 128];
        float a = g / sqrtf((float)var + 1e-5f);
        g_a[c] = a;
        if (c < 128) g_b2n[c] = be_ibn[c] - a * (float)mu;
    }
}

__global__ void k_wfold(const float* __restrict__ w_mr) {
    int i = blockIdx.x * 256 + threadIdx.x;
    g_Wfold[i] = w_mr[i] * g_a[i & 255];
}

// ============ GEMM-H: H[128][64px] = (Wfh+Wfl)[128x256] * Yh, 2 passes ========
#define H_AS   264
#define H_BS   72
#define H_ALO  67584u
#define H_B0   135168u
#define H_BSZ  36864u
#define SM_H   208896

__global__ __launch_bounds__(256, 1) void k_gemmH() {
    extern __shared__ __align__(16) char smem[];
    const uint32_t sb = smem_u32(smem);
    const int tid = threadIdx.x;
    const int lane = tid & 31, wid = tid >> 5;
    const int wr = wid >> 1, wc = wid & 1;
    const int cta = blockIdx.x;

    for (int idx = tid; idx < 128 * 256; idx += 256) {
        int m = idx >> 8, k = idx & 255;
        __half h, l; hsplit(g_Wfold[idx], h, l);
        *(__half*)(smem + (m * H_AS + k) * 2) = h;
        *(__half*)(smem + H_ALO + (m * H_AS + k) * 2) = l;
    }
    __syncthreads();

    const int la = lane & 15, lb = lane >> 4;
    const int mb = wr * 32, nb = wc * 32;
    const uint32_t aBase = sb + (uint32_t)((mb + la) * H_AS * 2 + lb * 16);
    const uint32_t bBase = sb + H_B0 + (uint32_t)(la * H_BS * 2 + (nb + lb * 8) * 2);

    float st1[4] = {0.f, 0.f, 0.f, 0.f}, st2[4] = {0.f, 0.f, 0.f, 0.f};
    int buf = 0;

    {
        int p0 = cta * 64;
        #pragma unroll
        for (int rq = 0; rq < 8; rq++) {
            int q = tid + rq * 256;
            int k = q >> 3, c8 = q & 7;
            CPA16(sb + H_B0 + (uint32_t)(k * H_BS * 2 + c8 * 16),
                  g_yh + (size_t)k * NPIX + p0 + c8 * 8);
        }
        CPC();
    }

    for (int t = cta; t < NT; t += NCTA) {
        int tn = t + NCTA;
        if (tn < NT) {
            int p0n = tn * 64;
            uint32_t bo = H_B0 + (uint32_t)(buf ^ 1) * H_BSZ;
            #pragma unroll
            for (int rq = 0; rq < 8; rq++) {
                int q = tid + rq * 256;
                int k = q >> 3, c8 = q & 7;
                CPA16(sb + bo + (uint32_t)(k * H_BS * 2 + c8 * 16),
                      g_yh + (size_t)k * NPIX + p0n + c8 * 8);
            }
        }
        CPC(); CPW1();
        __syncthreads();

        float c[2][4][4];
        #pragma unroll
        for (int i = 0; i < 2; i++)
            #pragma unroll
            for (int j = 0; j < 4; j++)
                #pragma unroll
                for (int q = 0; q < 4; q++) c[i][j][q] = 0.f;

        uint32_t bA = bBase + (uint32_t)buf * H_BSZ;
        #pragma unroll 1
        for (int p2 = 0; p2 < 2; p2++) {
            uint32_t aA = aBase + (p2 ? H_ALO : 0u);
            #pragma unroll
            for (int ks = 0; ks < 16; ks++) {
                uint32_t a0[4], a1[4], b0[4], b1[4];
                LDSM4(a0, aA + ks * 32);
                LDSM4(a1, aA + ks * 32 + 16 * H_AS * 2);
                LDSM4T(b0, bA + ks * (16 * H_BS * 2));
                LDSM4T(b1, bA + ks * (16 * H_BS * 2) + 32);
                MMA(c[0][0], a0, b0[0], b0[1]);
                MMA(c[0][1], a0, b0[2], b0[3]);
                MMA(c[0][2], a0, b1[0], b1[1]);
                MMA(c[0][3], a0, b1[2], b1[3]);
                MMA(c[1][0], a1, b0[0], b0[1]);
                MMA(c[1][1], a1, b0[2], b0[3]);
                MMA(c[1][2], a1, b1[0], b1[1]);
                MMA(c[1][3], a1, b1[2], b1[3]);
            }
        }
        __syncthreads();

        int p0 = t * 64;
        int r = lane >> 2, cq = (lane & 3) * 2;
        #pragma unroll
        for (int i = 0; i < 2; i++) {
            int chA = mb + i * 16 + r;
            float* gA = g_H + (size_t)chA * NPIX + p0;
            float* gB = gA + (size_t)8 * NPIX;
            #pragma unroll
            for (int j = 0; j < 4; j++) {
                int n = nb + j * 8 + cq;
                float v0 = c[i][j][0], v1 = c[i][j][1], v2 = c[i][j][2], v3 = c[i][j][3];
                st1[i * 2]     += v0 + v1; st2[i * 2]     += v0 * v0 + v1 * v1;
                st1[i * 2 + 1] += v2 + v3; st2[i * 2 + 1] += v2 * v2 + v3 * v3;
                float2 f0; f0.x = v0; f0.y = v1;
                float2 f1; f1.x = v2; f1.y = v3;
                *(float2*)(gA + n) = f0;
                *(float2*)(gB + n) = f1;
            }
        }
        buf ^= 1;           // <-- the Round-6 bug: this was missing
    }

    #pragma unroll
    for (int s = 0; s < 4; s++) {
        #pragma unroll
        for (int d = 1; d < 4; d <<= 1) {
            st1[s] += __shfl_xor_sync(0xffffffffu, st1[s], d);
            st2[s] += __shfl_xor_sync(0xffffffffu, st2[s], d);
        }
    }
    if ((lane & 3) == 0) {
        int r = lane >> 2;
        int col = cta * 2 + wc;
        #pragma unroll
        for (int s = 0; s < 4; s++) {
            int ch = wr * 32 + (s >> 1) * 16 + r + (s & 1) * 8;
            g_hpart[((size_t)ch * 296 + col) * 2 + 0] = st1[s];
            g_hpart[((size_t)ch * 296 + col) * 2 + 1] = st2[s];
        }
    }
}

// ---- reduce H stats -> a3, d3 ----
__global__ void k_reduceH(const float* __restrict__ g_mbn, const float* __restrict__ be_mbn) {
    int c = blockIdx.x, t = threadIdx.x;
    double s = 0.0, ss = 0.0;
    for (int i = t; i < 296; i += 128) {
        s  += (double)g_hpart[((size_t)c * 296 + i) * 2 + 0];
        ss += (double)g_hpart[((size_t)c * 296 + i) * 2 + 1];
    }
    __shared__ double sh[128], shh[128];
    sh[t] = s; shh[t] = ss; __syncthreads();
    for (int o = 64; o; o >>= 1) {
        if (t < o) { sh[t] += sh[t + o]; shh[t] += shh[t + o]; }
        __syncthreads();
    }
    if (t == 0) {
        double mu = sh[0] / (double)NPIX;
        double var = shh[0] / (double)NPIX - mu * mu;
        float a = g_mbn[c] / sqrtf((float)var + 1e-5f);
        g_a3[c] = a;
        g_d3[c] = be_mbn[c] - a * (float)mu;
    }
}

// ---- out = a2*(yh+yl) + b2n + gelu(a3*H + d3) ----
__global__ void k_out(float* __restrict__ out) {
    size_t i = ((size_t)blockIdx.x * 256 + threadIdx.x) * 4;
    int c = (int)((i >> 12) & 127);
    size_t b = i >> 19;
    size_t p = b * HW + (i & 4095);
    float4 h = *(const float4*)(g_H + (size_t)c * NPIX + p);
    __half2 yh0 = *(const __half2*)(g_yh + (size_t)c * NPIX + p);
    __half2 yh1 = *(const __half2*)(g_yh + (size_t)c * NPIX + p + 2);
    __half2 yl0 = *(const __half2*)(g_yl + (size_t)c * NPIX + p);
    __half2 yl1 = *(const __half2*)(g_yl + (size_t)c * NPIX + p + 2);
    float a2 = g_a[c], bn = g_b2n[c], a3 = g_a3[c], d3 = g_d3[c];
    float4 o;
    o.x = fmaf(a2, __half2float(yh0.x) + __half2float(yl0.x), bn) + gelu(fmaf(a3, h.x, d3));
    o.y = fmaf(a2, __half2float(yh0.y) + __half2float(yl0.y), bn) + gelu(fmaf(a3, h.y, d3));
    o.z = fmaf(a2, __half2float(yh1.x) + __half2float(yl1.x), bn) + gelu(fmaf(a3, h.z, d3));
    o.w = fmaf(a2, __half2float(yh1.y) + __half2float(yl1.y), bn) + gelu(fmaf(a3, h.w, d3));
    *(float4*)(out + i) = o;
}

extern "C" void kernel_launch(void* const* d_in, const int* in_sizes, int n_in,
                              void* d_out, int out_size) {
    const float* x      = (const float*)d_in[0];
    const float* w_diff = (const float*)d_in[1];
    const float* gbn    = (const float*)d_in[3];
    const float* w_in   = (const float*)d_in[5];
    const float* g_ibn  = (const float*)d_in[7];
    const float* be_ibn = (const float*)d_in[8];
    const float* w_mr   = (const float*)d_in[9];
    const float* g_mbn  = (const float*)d_in[11];
    const float* be_mbn = (const float*)d_in[12];
    float* out = (float*)d_out;

    cudaFuncSetAttribute(k_gemmY, cudaFuncAttributeMaxDynamicSharedMemorySize, SM_Y);
    cudaFuncSetAttribute(k_gemmH, cudaFuncAttributeMaxDynamicSharedMemorySize, SM_H);

    k_fmax<<<4096, 256>>>(x);
    k_gemmY<<<dim3(NCTA, 2), 256, SM_Y>>>(w_in, w_diff);
    k_reduceY<<<256, 128>>>(g_ibn, be_ibn, gbn);
    k_wfold<<<128, 256>>>(w_mr);
    k_gemmH<<<NCTA, 256, SM_H>>>();
    k_reduceH<<<128, 128>>>(g_mbn, be_mbn);
    k_out<<<16384, 256>>>(out);
}